// round 16
// baseline (speedup 1.0000x reference)
#include <cuda_runtime.h>
#include <cuda.h>
#include <math.h>
#include <stdint.h>

// ---------------- problem constants ----------------
#define CC    1024           // model dim
#define NE    8              // experts
#define FF    2752           // ffn dim
#define FP    2816           // ffn dim padded to 128*22
#define NT    8192           // tokens
#define NRR   16384          // routed rows (NT*2)
#define RMAX2 18432          // NRR + NE*256 (per-expert pad to 256)
#define PT    72             // pair tiles (RMAX2/256)
#define MT_FB 144            // 128-row tiles (fallback)
#define NK1   32             // CC/32 k-steps (gemm1)
#define NK2   88             // FP/32 k-steps (gemm2)
#define ST1   4              // pipeline stages gemm1 (cg2, 48KB stages)
#define ST2   3              // pipeline stages gemm2
#define STAGE1 49152         // per-CTA: A-half 16KB + Bg-half 16KB + Bu-half 16KB
#define TX1    98304         // leader-barrier tx: both CTAs' 48KB
#define STAGE2 65536         // A 32KB + B 32KB (N=256)
#define IDESC_TF32      0x8200910u  // cF32|aTF32|bTF32|(128/8)<<17|(128/16)<<24
#define IDESC_TF32_N256 0x8400910u  // N=256 (gemm2)
#define IDESC_CG2       0x10400910u // cg2: M=256 -> 16<<24, N=256 -> 32<<17
// fused prep grid layout
#define NB_TR1   (86 * 32 * NE)
#define NB_TR    (3 * NB_TR1)
#define NB_ROW   (RMAX2 / 256)
#define NB_GATE  (NT / 8)
#define NB_PREP  (NB_TR + NB_ROW + NB_GATE)
// fallback tiling
#define BMF  128
#define BNF  64
#define BKF  16
#define SA   20
#define SBS  72

#if defined(__CUDA_ARCH_FEAT_SM103_ALL) || defined(__CUDA_ARCH_FEAT_SM100_ALL) || \
    defined(__CUDA_ARCH_FEAT_SM101_ALL) || defined(__CUDA_ARCH_FAMILY_SPECIFIC__)
#define TC_ENABLED 1
#else
#define TC_ENABLED 0
#endif

// ---------------- scratch (__device__ globals) ----------------
__device__ int   g_tc;
__device__ int   g_count[NE];
__device__ int   g_cursor[NE];
__device__ int   g_off[NE + 1];
__device__ int   g_tile_expert[PT];
__device__ int   g_tok_e[NRR];
__device__ float g_tok_w[NRR];
__device__ int   g_row_token[RMAX2];
__device__ float g_row_weight[RMAX2];
__device__ int   g_row_of[NRR];
__device__ __align__(1024) float g_gx[(size_t)RMAX2 * CC];
__device__ __align__(1024) float g_wgT[(size_t)NE * FF * CC];
__device__ __align__(1024) float g_wuT[(size_t)NE * FF * CC];
__device__ __align__(1024) float g_wdT[(size_t)NE * CC * FF];
__device__ __align__(1024) float g_h[(size_t)RMAX2 * FP];
__device__ __align__(1024) float g_y[(size_t)RMAX2 * CC];

// ---------------- PTX helpers ----------------
__device__ __forceinline__ float f2tf(float x) {
    unsigned u; asm("cvt.rna.tf32.f32 %0, %1;" : "=r"(u) : "f"(x));
    return __uint_as_float(u);
}
__device__ __forceinline__ uint32_t smem_u32(const void* p) {
    uint32_t a;
    asm("{ .reg .u64 t; cvta.to.shared.u64 t, %1; cvt.u32.u64 %0, t; }" : "=r"(a) : "l"(p));
    return a;
}
#if TC_ENABLED
__device__ __forceinline__ uint32_t elect_one() {
    uint32_t p;
    asm volatile("{ .reg .pred p; elect.sync _|p, 0xFFFFFFFF; selp.b32 %0, 1, 0, p; }" : "=r"(p));
    return p;
}
__device__ __forceinline__ uint32_t cluster_rank() {
    uint32_t r; asm("mov.u32 %0, %%cluster_ctarank;" : "=r"(r)); return r;
}
#define CLUSTER_SYNC() do { \
    asm volatile("barrier.cluster.arrive.aligned;" ::: "memory"); \
    asm volatile("barrier.cluster.wait.aligned;" ::: "memory"); } while (0)
#define MBAR_INIT(a, n) asm volatile("mbarrier.init.shared.b64 [%0], %1;" :: "r"(a), "r"((uint32_t)(n)) : "memory")
#define MBAR_EXPECT_TX(a, b) asm volatile("mbarrier.arrive.expect_tx.shared.b64 _, [%0], %1;" :: "r"(a), "r"((uint32_t)(b)) : "memory")
#define MBAR_WAIT(a, p) do { \
    uint32_t _m = (a), _p = (p), _d; \
    asm volatile("{ .reg .pred q; mbarrier.try_wait.parity.acquire.cta.shared::cta.b64 q, [%1], %2; selp.b32 %0, 1, 0, q; }" \
        : "=r"(_d) : "r"(_m), "r"(_p) : "memory"); \
    if (!_d) { \
        asm volatile("{ .reg .pred Q;\nWL%=:\n mbarrier.try_wait.parity.acquire.cta.shared::cta.b64 Q, [%0], %1, 0x989680;\n @Q bra.uni WD%=;\n bra.uni WL%=;\nWD%=:\n}" \
            :: "r"(_m), "r"(_p) : "memory"); \
    } } while (0)
#define FENCE_ASYNC() asm volatile("fence.proxy.async.shared::cta;" ::: "memory")
#define TMA_2D(sm, mp, c0, c1, mb) \
    asm volatile("cp.async.bulk.tensor.2d.shared::cta.global.tile.mbarrier::complete_tx::bytes [%0], [%1, {%2, %3}], [%4];" \
        :: "r"(sm), "l"(mp), "r"(c0), "r"(c1), "r"(mb) : "memory")
#define TMA_3D(sm, mp, c0, c1, c2, mb) \
    asm volatile("cp.async.bulk.tensor.3d.shared::cta.global.tile.mbarrier::complete_tx::bytes [%0], [%1, {%2, %3, %4}], [%5];" \
        :: "r"(sm), "l"(mp), "r"(c0), "r"(c1), "r"(c2), "r"(mb) : "memory")
// cg2 TMA: both CTAs load their own smem halves; complete_tx targets CTA0's barrier
#define TMA_3D_CG2(sm, mp, c0, c1, c2, mb) \
    asm volatile("{\n .reg .b32 lb;\n and.b32 lb, %5, 0xFEFFFFFF;\n" \
        "cp.async.bulk.tensor.3d.cta_group::2.shared::cluster.global.tile.mbarrier::complete_tx::bytes [%0], [%1, {%2, %3, %4}], [lb];\n}" \
        :: "r"(sm), "l"(mp), "r"(c0), "r"(c1), "r"(c2), "r"(mb) : "memory")
#define TC_ALLOC(sm, n)   asm volatile("tcgen05.alloc.cta_group::1.sync.aligned.shared::cta.b32 [%0], %1;" :: "r"(sm), "r"((uint32_t)(n)) : "memory")
#define TC_DEALLOC(t, n)  asm volatile("tcgen05.dealloc.cta_group::1.sync.aligned.b32 %0, %1;" :: "r"(t), "r"((uint32_t)(n)))
#define TC_ALLOC_CG2(sm, n)  asm volatile("tcgen05.alloc.cta_group::2.sync.aligned.shared::cta.b32 [%0], %1;" :: "r"(sm), "r"((uint32_t)(n)) : "memory")
#define TC_DEALLOC_CG2(t, n) asm volatile("tcgen05.dealloc.cta_group::2.sync.aligned.b32 %0, %1;" :: "r"(t), "r"((uint32_t)(n)))
#define TC_COMMIT(mb)     asm volatile("tcgen05.commit.cta_group::1.mbarrier::arrive::one.shared::cluster.b64 [%0];" :: "r"(mb) : "memory")
#define TC_COMMIT_CG2_MCAST(mb, mask) \
    asm volatile("tcgen05.commit.cta_group::2.mbarrier::arrive::one.shared::cluster.multicast::cluster.b64 [%0], %1;" \
        :: "r"(mb), "h"((uint16_t)(mask)) : "memory")
#define TC_FENCE_AFTER()  asm volatile("tcgen05.fence::after_thread_sync;" ::: "memory")
#define TC_FENCE_BEFORE() asm volatile("tcgen05.fence::before_thread_sync;" ::: "memory")
#define TC_WAIT_LD()      asm volatile("tcgen05.wait::ld.sync.aligned;" ::: "memory")
#define TC_MMA(d, ad, bd, idsc, en) do { \
    uint32_t _e = (en) ? 1u : 0u, _z = 0u; \
    asm volatile("{ .reg .pred p; setp.ne.u32 p, %5, 0;\n" \
        "tcgen05.mma.cta_group::1.kind::tf32 [%0], %1, %2, %3, {%4, %4, %4, %4}, p;\n}" \
        :: "r"(d), "l"(ad), "l"(bd), "r"(idsc), "r"(_z), "r"(_e) : "memory"); \
    } while (0)
#define TC_MMA_CG2(d, ad, bd, idsc, en) do { \
    uint32_t _e = (en) ? 1u : 0u, _z = 0u; \
    asm volatile("{ .reg .pred p; setp.ne.u32 p, %5, 0;\n" \
        "tcgen05.mma.cta_group::2.kind::tf32 [%0], %1, %2, %3, {%4, %4, %4, %4, %4, %4, %4, %4}, p;\n}" \
        :: "r"(d), "l"(ad), "l"(bd), "r"(idsc), "r"(_z), "r"(_e) : "memory"); \
    } while (0)
#define TC_LD_X32(r, t) \
    asm volatile("tcgen05.ld.sync.aligned.32x32b.x32.b32 " \
        "{%0,%1,%2,%3,%4,%5,%6,%7,%8,%9,%10,%11,%12,%13,%14,%15," \
        "%16,%17,%18,%19,%20,%21,%22,%23,%24,%25,%26,%27,%28,%29,%30,%31}, [%32];" \
        : "=r"((r)[0]),"=r"((r)[1]),"=r"((r)[2]),"=r"((r)[3]),"=r"((r)[4]),"=r"((r)[5]),"=r"((r)[6]),"=r"((r)[7]), \
          "=r"((r)[8]),"=r"((r)[9]),"=r"((r)[10]),"=r"((r)[11]),"=r"((r)[12]),"=r"((r)[13]),"=r"((r)[14]),"=r"((r)[15]), \
          "=r"((r)[16]),"=r"((r)[17]),"=r"((r)[18]),"=r"((r)[19]),"=r"((r)[20]),"=r"((r)[21]),"=r"((r)[22]),"=r"((r)[23]), \
          "=r"((r)[24]),"=r"((r)[25]),"=r"((r)[26]),"=r"((r)[27]),"=r"((r)[28]),"=r"((r)[29]),"=r"((r)[30]),"=r"((r)[31]) \
        : "r"(t))

static __device__ __forceinline__ uint64_t mk_desc(uint32_t addr) {
    // SW128, version=1 (Blackwell), SBO=64, LBO=1  (128B rows, 1024B atoms)
    uint64_t d = (uint64_t(2) << 61) | (uint64_t(1) << 46) | (uint64_t(64) << 32) | (uint64_t(1) << 16);
    return d | ((uint64_t)(addr >> 4) & 0x3FFF);
}
#endif  // TC_ENABLED

// legacy mma.sync tf32 (works on any pass)
__device__ __forceinline__ void mma_tf32_legacy(float d[4], const float a[4], const float b[2]) {
    asm volatile(
        "mma.sync.aligned.m16n8k8.row.col.f32.tf32.tf32.f32 "
        "{%0,%1,%2,%3}, {%4,%5,%6,%7}, {%8,%9}, {%0,%1,%2,%3};\n"
        : "+f"(d[0]), "+f"(d[1]), "+f"(d[2]), "+f"(d[3])
        : "r"(__float_as_uint(a[0])), "r"(__float_as_uint(a[1])),
          "r"(__float_as_uint(a[2])), "r"(__float_as_uint(a[3])),
          "r"(__float_as_uint(b[0])), "r"(__float_as_uint(b[1])));
}

// ---------------- 0a. init0 ----------------
__global__ void init0_kernel() {
    int i = threadIdx.x;
    if (i < NE) { g_count[i] = 0; g_cursor[i] = 0; }
    if (i == 0) g_tc = 0;
}

// ---------------- 0b. fused prep: row-init + gate + 3 transposes --------------
__global__ __launch_bounds__(256) void prep_kernel(
    const float* __restrict__ x, const float* __restrict__ wgate,
    const float* __restrict__ wg, const float* __restrict__ wu,
    const float* __restrict__ wd,
    float* __restrict__ wgT, float* __restrict__ wuT, float* __restrict__ wdT)
{
    __shared__ float sw[NE * CC];
    __shared__ float tt[32][33];

    const int b = blockIdx.x;
    const int tid = threadIdx.x;

    if (b < NB_TR) {
        int which = b / NB_TR1;
        int rem = b % NB_TR1;
        const float* in; float* out; int R, Q, bx, by, e;
        if (which < 2) {
            in = (which == 0) ? wg : wu;
            out = (which == 0) ? wgT : wuT;
            R = CC; Q = FF;
            bx = rem % 86; by = (rem / 86) % 32; e = rem / (86 * 32);
        } else {
            in = wd; out = wdT;
            R = FF; Q = CC;
            bx = rem % 32; by = (rem / 32) % 86; e = rem / (32 * 86);
        }
        const float* src = in + (size_t)e * R * Q;
        float* dst = out + (size_t)e * R * Q;
        int r0 = by * 32, q0 = bx * 32;
        int tx = tid & 31, ty = tid >> 5;
#pragma unroll
        for (int i = ty; i < 32; i += 8)
            tt[i][tx] = src[(size_t)(r0 + i) * Q + q0 + tx];
        __syncthreads();
#pragma unroll
        for (int i = ty; i < 32; i += 8)
            dst[(size_t)(q0 + i) * R + r0 + tx] = f2tf(tt[tx][i]);
        return;
    }
    if (b < NB_TR + NB_ROW) {
        int i = (b - NB_TR) * 256 + tid;
        if (i < RMAX2) { g_row_token[i] = -1; g_row_weight[i] = 0.f; }
        return;
    }
    {
        int gb = b - NB_TR - NB_ROW;
        for (int i = tid * 4; i < NE * CC; i += 256 * 4)
            *(float4*)&sw[i] = *(const float4*)&wgate[i];
        __syncthreads();
        int warp = tid >> 5, lane = tid & 31;
        int t = gb * 8 + warp;
        const float* xt = x + (size_t)t * CC;
        float acc[NE];
#pragma unroll
        for (int e = 0; e < NE; e++) acc[e] = 0.f;
        for (int j = lane; j < CC; j += 32) {
            float xv = xt[j];
#pragma unroll
            for (int e = 0; e < NE; e++) acc[e] += xv * sw[e * CC + j];
        }
#pragma unroll
        for (int off = 16; off > 0; off >>= 1)
#pragma unroll
            for (int e = 0; e < NE; e++) acc[e] += __shfl_xor_sync(0xffffffffu, acc[e], off);
        if (lane == 0) {
            float m = acc[0];
#pragma unroll
            for (int e = 1; e < NE; e++) m = fmaxf(m, acc[e]);
            float p[NE], s = 0.f;
#pragma unroll
            for (int e = 0; e < NE; e++) { p[e] = expf(acc[e] - m); s += p[e]; }
            int i0 = 0; float b0 = p[0];
#pragma unroll
            for (int e = 1; e < NE; e++) if (p[e] > b0) { b0 = p[e]; i0 = e; }
            int i1 = -1; float b1 = -1.f;
#pragma unroll
            for (int e = 0; e < NE; e++) if (e != i0 && p[e] > b1) { b1 = p[e]; i1 = e; }
            float s0 = b0 / s, s1 = b1 / s;
            float den = s0 + s1 + 1e-9f;
            g_tok_e[2 * t] = i0;     g_tok_w[2 * t] = s0 / den;
            g_tok_e[2 * t + 1] = i1; g_tok_w[2 * t + 1] = s1 / den;
            atomicAdd(&g_count[i0], 1);
            atomicAdd(&g_count[i1], 1);
        }
    }
}

// ---------------- 2. scan ----------------
__global__ void scan_kernel() {
    if (threadIdx.x == 0 && blockIdx.x == 0) {
        int off = 0;
        for (int e = 0; e < NE; e++) {
            g_off[e] = off;
            off += ((g_count[e] + 255) / 256) * 256;
        }
        g_off[NE] = off;
        int tl = 0;
        for (int e = 0; e < NE; e++) {
            int pairs = (g_off[e + 1] - g_off[e]) / 256;
            for (int i = 0; i < pairs; i++) g_tile_expert[tl++] = e;
        }
        while (tl < PT) g_tile_expert[tl++] = 0;
    }
}

// ---------------- 3. fused assign + permute ----------------
__global__ __launch_bounds__(256) void assign_permute_kernel(const float* __restrict__ x) {
    int warp = threadIdx.x >> 5, lane = threadIdx.x & 31;
    int t = blockIdx.x * 8 + warp;
    int row0 = 0, row1 = 0;
    if (lane == 0) {
        int e0 = g_tok_e[2 * t];
        int p0 = atomicAdd(&g_cursor[e0], 1);
        row0 = g_off[e0] + p0;
        g_row_token[row0] = t;
        g_row_weight[row0] = g_tok_w[2 * t];
        g_row_of[2 * t] = row0;
        int e1 = g_tok_e[2 * t + 1];
        int p1 = atomicAdd(&g_cursor[e1], 1);
        row1 = g_off[e1] + p1;
        g_row_token[row1] = t;
        g_row_weight[row1] = g_tok_w[2 * t + 1];
        g_row_of[2 * t + 1] = row1;
    }
    row0 = __shfl_sync(0xffffffffu, row0, 0);
    row1 = __shfl_sync(0xffffffffu, row1, 0);
    const float4* xs = (const float4*)(x + (size_t)t * CC);
    float4* d0 = (float4*)(g_gx + (size_t)row0 * CC);
    float4* d1 = (float4*)(g_gx + (size_t)row1 * CC);
#pragma unroll
    for (int i = lane; i < CC / 4; i += 32) {
        float4 v = xs[i];
        v.x = f2tf(v.x); v.y = f2tf(v.y); v.z = f2tf(v.z); v.w = f2tf(v.w);
        d0[i] = v;
        d1[i] = v;
    }
}

// ---------------- 6. GEMM1 (tcgen05 cg2): h = silu(gx@wg)*(gx@wu) -------------
// cluster-2 cooperative MMA: tile M=256 x N=256 per CTA pair. Each CTA holds
// its 128 A-rows + 128 B-cols per operand (48KB stages, ST1=4). rank0 issues
// cg2 MMAs over both CTAs' smem; commits multicast to both EMPTYs.
__global__ __launch_bounds__(128, 1) void gemm1_kernel(
    const __grid_constant__ CUtensorMap tma_a,    // 3D, box 32 x 128
    const __grid_constant__ CUtensorMap tma_bg,
    const __grid_constant__ CUtensorMap tma_bu)
{
#if TC_ENABLED
    extern __shared__ char smem[];
    uint32_t sb = smem_u32(smem);
    uint32_t TMP = sb;
    uint32_t FULL = sb + 8;
    uint32_t EMPTY = sb + 8 + 8 * ST1;
    uint32_t DONE = sb + 8 + 16 * ST1;
    uint32_t tiles = (sb + 80 + 1023) & ~1023u;

    const int ftile = blockIdx.x >> 1;            // 0..10 (256-wide f tiles)
    const int pair = blockIdx.y;
    const int e = g_tile_expert[pair];
    const int tid = threadIdx.x, wid = tid >> 5, lane = tid & 31;
    const uint32_t rank = cluster_rank();

    if (tid == 0) {
        g_tc = 1;
        for (int s = 0; s < ST1; s++) { MBAR_INIT(FULL + 8 * s, 1); MBAR_INIT(EMPTY + 8 * s, 1); }
        MBAR_INIT(DONE, 1);
        FENCE_ASYNC();
    }
    if (wid == 0) TC_ALLOC_CG2(TMP, 512);
    __syncthreads();
    CLUSTER_SYNC();   // peer barriers visible before any cg2 TMA/commit targets them
    uint32_t tmem;
    asm volatile("ld.shared.b32 %0, [%1];" : "=r"(tmem) : "r"(TMP));

    if (wid == 0 && elect_one()) {
        // each CTA loads ITS half-tiles; completion lands on rank0's FULL
        auto tma_own = [&](int s, int ks) {
            uint32_t a = tiles + s * STAGE1;
            TMA_3D_CG2(a,         &tma_a,  ks * 32, pair * 256 + (int)rank * 128, 0, FULL + 8 * s);
            TMA_3D_CG2(a + 16384, &tma_bg, ks * 32, ftile * 256 + (int)rank * 128, e, FULL + 8 * s);
            TMA_3D_CG2(a + 32768, &tma_bu, ks * 32, ftile * 256 + (int)rank * 128, e, FULL + 8 * s);
        };
        if (rank == 0) {
            for (int j = 0; j < ST1; j++) { MBAR_EXPECT_TX(FULL + 8 * j, TX1); tma_own(j, j); }
            for (int i = 0; i < NK1; i++) {
                int s = i % ST1;
                MBAR_WAIT(FULL + 8 * s, (uint32_t)(i / ST1) & 1);
                uint64_t ad = mk_desc(tiles + s * STAGE1);
                uint64_t bg = mk_desc(tiles + s * STAGE1 + 16384);
                uint64_t bu = mk_desc(tiles + s * STAGE1 + 32768);
#pragma unroll
                for (int k8 = 0; k8 < 4; k8++) {
                    bool en = (i > 0) || (k8 > 0);
                    TC_MMA_CG2(tmem + 0,   ad + k8 * 2, bg + k8 * 2, IDESC_CG2, en);
                    TC_MMA_CG2(tmem + 256, ad + k8 * 2, bu + k8 * 2, IDESC_CG2, en);
                }
                TC_COMMIT_CG2_MCAST(EMPTY + 8 * s, 0x3);
                if (i >= 1 && i <= NK1 - ST1) {
                    int s2 = (i - 1) % ST1;
                    MBAR_WAIT(EMPTY + 8 * s2, (uint32_t)((i - 1) / ST1) & 1);
                    MBAR_EXPECT_TX(FULL + 8 * s2, TX1);
                    tma_own(s2, (i - 1) + ST1);
                }
            }
            TC_COMMIT_CG2_MCAST(DONE, 0x3);
        } else {
            for (int j = 0; j < ST1; j++) tma_own(j, j);
            for (int j = ST1; j < NK1; j++) {
                int s = j % ST1;
                MBAR_WAIT(EMPTY + 8 * s, (uint32_t)((j - ST1) / ST1) & 1);
                tma_own(s, j);
            }
        }
    }
    __syncthreads();
    MBAR_WAIT(DONE, 0);
    TC_FENCE_AFTER();

    // epilogue: this CTA's TMEM holds rows rank*128..rank*128+127, 256 g + 256 u cols
    {
        int row = pair * 256 + (int)rank * 128 + wid * 32 + lane;
        size_t hb = (size_t)row * FP + ftile * 256;
#pragma unroll
        for (int c = 0; c < 8; c++) {
            uint32_t gr[32], ur[32];
            TC_LD_X32(gr, tmem + c * 32);
            TC_LD_X32(ur, tmem + 256 + c * 32);
            TC_WAIT_LD();
            float buf[32];
#pragma unroll
            for (int q = 0; q < 32; q++) {
                float g = __uint_as_float(gr[q]);
                float u = __uint_as_float(ur[q]);
                buf[q] = f2tf(g / (1.f + expf(-g)) * u);
            }
#pragma unroll
            for (int q = 0; q < 32; q += 4)
                *(float4*)&g_h[hb + c * 32 + q] = make_float4(buf[q], buf[q+1], buf[q+2], buf[q+3]);
        }
    }
    TC_FENCE_BEFORE();
    __syncthreads();
    if (wid == 0) TC_DEALLOC_CG2(tmem, 512);
    CLUSTER_SYNC();   // no CTA exits while peer ops targeting it may be in flight
#endif
}

// ---------------- 7. GEMM2 (tcgen05): y = weight * (h @ wd), N=256 ------------
// unchanged from the 831us version
__global__ __launch_bounds__(128, 1) void gemm2_kernel(
    const __grid_constant__ CUtensorMap tma_a,
    const __grid_constant__ CUtensorMap tma_b)
{
#if TC_ENABLED
    extern __shared__ char smem[];
    uint32_t sb = smem_u32(smem);
    uint32_t TMP = sb;
    uint32_t FULL = sb + 8;
    uint32_t EMPTY = sb + 8 + 8 * ST2;
    uint32_t DONE = sb + 8 + 16 * ST2;
    uint32_t tiles = (sb + 80 + 1023) & ~1023u;

    const int ctile = blockIdx.x;
    const int pair = blockIdx.y;
    const int e = g_tile_expert[pair];
    const int tid = threadIdx.x, wid = tid >> 5, lane = tid & 31;

    if (tid == 0) {
        for (int s = 0; s < ST2; s++) { MBAR_INIT(FULL + 8 * s, 1); MBAR_INIT(EMPTY + 8 * s, 1); }
        MBAR_INIT(DONE, 1);
        FENCE_ASYNC();
    }
    if (wid == 0) TC_ALLOC(TMP, 512);
    __syncthreads();
    uint32_t tmem;
    asm volatile("ld.shared.b32 %0, [%1];" : "=r"(tmem) : "r"(TMP));

    if (wid == 0 && elect_one()) {
        auto tma_stage = [&](int s, int ks) {
            uint32_t a = tiles + s * STAGE2;
            MBAR_EXPECT_TX(FULL + 8 * s, STAGE2);
            TMA_2D(a,         &tma_a, ks * 32, pair * 256, FULL + 8 * s);
            TMA_3D(a + 32768, &tma_b, ks * 32, ctile * 256, e, FULL + 8 * s);
        };
        for (int j = 0; j < ST2; j++) tma_stage(j, j);
        for (int i = 0; i < NK2; i++) {
            int s = i % ST2;
            MBAR_WAIT(FULL + 8 * s, (uint32_t)(i / ST2) & 1);
            uint64_t ad = mk_desc(tiles + s * STAGE2);
            uint64_t bd = mk_desc(tiles + s * STAGE2 + 32768);
#pragma unroll
            for (int k8 = 0; k8 < 4; k8++) {
                bool en = (i > 0) || (k8 > 0);
                TC_MMA(tmem + 0,   ad + k8 * 2,        bd + k8 * 2, IDESC_TF32_N256, en);
                TC_MMA(tmem + 256, ad + 1024 + k8 * 2, bd + k8 * 2, IDESC_TF32_N256, en);
            }
            TC_COMMIT(EMPTY + 8 * s);
            if (i >= 1 && i <= NK2 - ST2) {
                int s2 = (i - 1) % ST2;
                MBAR_WAIT(EMPTY + 8 * s2, (uint32_t)((i - 1) / ST2) & 1);
                tma_stage(s2, (i - 1) + ST2);
            }
        }
        TC_COMMIT(DONE);
    }
    __syncthreads();
    MBAR_WAIT(DONE, 0);
    TC_FENCE_AFTER();

#pragma unroll
    for (int m = 0; m < 2; m++) {
        int row = pair * 256 + m * 128 + wid * 32 + lane;
        float w = g_row_weight[row];
        size_t yb = (size_t)row * CC + ctile * 256;
#pragma unroll
        for (int c = 0; c < 8; c++) {
            uint32_t yr[32];
            TC_LD_X32(yr, tmem + m * 256 + c * 32);
            TC_WAIT_LD();
            float buf[32];
#pragma unroll
            for (int q = 0; q < 32; q++) buf[q] = __uint_as_float(yr[q]) * w;
#pragma unroll
            for (int q = 0; q < 32; q += 4)
                *(float4*)&g_y[yb + c * 32 + q] = make_float4(buf[q], buf[q+1], buf[q+2], buf[q+3]);
        }
    }
    TC_FENCE_BEFORE();
    __syncthreads();
    if (wid == 0) TC_DEALLOC(tmem, 512);
#endif
}

// ---------------- 6b. GEMM1 fallback (mma.sync, validated) --------------------
__global__ __launch_bounds__(256) void gemm1_fb_kernel(
    const float* __restrict__ x, const float* __restrict__ wg, const float* __restrict__ wu)
{
    if (g_tc != 0) return;
    __shared__ float As[2][BMF * SA];
    __shared__ float Bgs[2][BKF * SBS];
    __shared__ float Bus[2][BKF * SBS];
    __shared__ int stok[BMF];

    const int ftile = blockIdx.x;
    const int mtile = blockIdx.y;
    const int tid = threadIdx.x;
    const int e = g_tile_expert[mtile >> 1];
    const float* wgE = wg + (size_t)e * CC * FF;
    const float* wuE = wu + (size_t)e * CC * FF;

    if (tid < BMF) stok[tid] = g_row_token[mtile * BMF + tid];
    __syncthreads();

    const int warp = tid >> 5, lane = tid & 31;
    const int wm = warp >> 1, wn = warp & 1;
    const int gid = lane >> 2, tig = lane & 3;
    const int am0 = tid >> 2, ak0 = (tid & 3) * 4;
    const int am1 = (tid + 256) >> 2;
    const int bk = tid >> 4, bfi = (tid & 15) * 4;
    const int fbase = ftile * BNF;

    float4 ra0, ra1, rbg, rbu;
    auto stage_load = [&](int ks) {
        int kb = ks * BKF;
        int t0 = stok[am0];
        ra0 = make_float4(0.f, 0.f, 0.f, 0.f);
        if (t0 >= 0) ra0 = *(const float4*)(x + (size_t)t0 * CC + kb + ak0);
        int t1 = stok[am1];
        ra1 = make_float4(0.f, 0.f, 0.f, 0.f);
        if (t1 >= 0) ra1 = *(const float4*)(x + (size_t)t1 * CC + kb + ak0);
        rbg = *(const float4*)(wgE + (size_t)(kb + bk) * FF + fbase + bfi);
        rbu = *(const float4*)(wuE + (size_t)(kb + bk) * FF + fbase + bfi);
        rbg.x = f2tf(rbg.x); rbg.y = f2tf(rbg.y); rbg.z = f2tf(rbg.z); rbg.w = f2tf(rbg.w);
        rbu.x = f2tf(rbu.x); rbu.y = f2tf(rbu.y); rbu.z = f2tf(rbu.z); rbu.w = f2tf(rbu.w);
    };
    auto stage_store = [&](int buf) {
        float* a0 = &As[buf][am0 * SA + ak0];
        a0[0] = f2tf(ra0.x); a0[1] = f2tf(ra0.y); a0[2] = f2tf(ra0.z); a0[3] = f2tf(ra0.w);
        float* a1 = &As[buf][am1 * SA + ak0];
        a1[0] = f2tf(ra1.x); a1[1] = f2tf(ra1.y); a1[2] = f2tf(ra1.z); a1[3] = f2tf(ra1.w);
        *(float4*)&Bgs[buf][bk * SBS + bfi] = rbg;
        *(float4*)&Bus[buf][bk * SBS + bfi] = rbu;
    };

    float accg[2][4][4], accu[2][4][4];
#pragma unroll
    for (int i = 0; i < 2; i++)
#pragma unroll
        for (int j = 0; j < 4; j++)
#pragma unroll
            for (int q = 0; q < 4; q++) { accg[i][j][q] = 0.f; accu[i][j][q] = 0.f; }

    stage_load(0);
    stage_store(0);
    __syncthreads();

    const int nst = CC / BKF;
    for (int ks = 0; ks < nst; ks++) {
        int buf = ks & 1;
        if (ks + 1 < nst) stage_load(ks + 1);
#pragma unroll
        for (int kk = 0; kk < BKF; kk += 8) {
            float a[2][4];
#pragma unroll
            for (int mt = 0; mt < 2; mt++) {
                int rb = wm * 32 + mt * 16;
                a[mt][0] = As[buf][(rb + gid)     * SA + kk + tig];
                a[mt][1] = As[buf][(rb + gid + 8) * SA + kk + tig];
                a[mt][2] = As[buf][(rb + gid)     * SA + kk + tig + 4];
                a[mt][3] = As[buf][(rb + gid + 8) * SA + kk + tig + 4];
            }
            float bg[4][2], bu[4][2];
#pragma unroll
            for (int nt = 0; nt < 4; nt++) {
                int cb = wn * 32 + nt * 8 + gid;
                bg[nt][0] = Bgs[buf][(kk + tig)     * SBS + cb];
                bg[nt][1] = Bgs[buf][(kk + tig + 4) * SBS + cb];
                bu[nt][0] = Bus[buf][(kk + tig)     * SBS + cb];
                bu[nt][1] = Bus[buf][(kk + tig + 4) * SBS + cb];
            }
#pragma unroll
            for (int mt = 0; mt < 2; mt++)
#pragma unroll
                for (int nt = 0; nt < 4; nt++) {
                    mma_tf32_legacy(accg[mt][nt], a[mt], bg[nt]);
                    mma_tf32_legacy(accu[mt][nt], a[mt], bu[nt]);
                }
        }
        if (ks + 1 < nst) stage_store(buf ^ 1);
        __syncthreads();
    }

    const int rb0 = mtile * BMF + wm * 32;
    const int cb0 = ftile * BNF + wn * 32;
#pragma unroll
    for (int mt = 0; mt < 2; mt++) {
        int r0 = rb0 + mt * 16 + gid;
#pragma unroll
        for (int nt = 0; nt < 4; nt++) {
            int c = cb0 + nt * 8 + tig * 2;
            float g0 = accg[mt][nt][0], g1 = accg[mt][nt][1];
            float g2 = accg[mt][nt][2], g3 = accg[mt][nt][3];
            float h0 = g0 / (1.f + expf(-g0)) * accu[mt][nt][0];
            float h1 = g1 / (1.f + expf(-g1)) * accu[mt][nt][1];
            float h2 = g2 / (1.f + expf(-g2)) * accu[mt][nt][2];
            float h3 = g3 / (1.f + expf(-g3)) * accu[mt][nt][3];
            *(float2*)&g_h[(size_t)r0 * FP + c]       = make_float2(h0, h1);
            *(float2*)&g_h[(size_t)(r0 + 8) * FP + c] = make_float2(h2, h3);
        }
    }
}

// ---------------- 7b. GEMM2 fallback ------------------------------------------
__global__ __launch_bounds__(256) void gemm2_fb_kernel(const float* __restrict__ wd)
{
    if (g_tc != 0) return;
    __shared__ float As[2][BMF * SA];
    __shared__ float Bs[2][BKF * SBS];

    const int ctile = blockIdx.x;
    const int mtile = blockIdx.y;
    const int tid = threadIdx.x;
    const int e = g_tile_expert[mtile >> 1];
    const float* wdE = wd + (size_t)e * FF * CC;

    const int warp = tid >> 5, lane = tid & 31;
    const int wm = warp >> 1, wn = warp & 1;
    const int gid = lane >> 2, tig = lane & 3;
    const int am0 = tid >> 2, ak0 = (tid & 3) * 4;
    const int am1 = (tid + 256) >> 2;
    const int bk = tid >> 4, bfi = (tid & 15) * 4;
    const int cbase = ctile * BNF;
    const size_t hrow0 = (size_t)(mtile * BMF + am0) * FP;
    const size_t hrow1 = (size_t)(mtile * BMF + am1) * FP;

    float4 ra0, ra1, rb;
    auto stage_load = [&](int ks) {
        int kb = ks * BKF;
        ra0 = *(const float4*)(g_h + hrow0 + kb + ak0);
        ra1 = *(const float4*)(g_h + hrow1 + kb + ak0);
        rb  = *(const float4*)(wdE + (size_t)(kb + bk) * CC + cbase + bfi);
        rb.x = f2tf(rb.x); rb.y = f2tf(rb.y); rb.z = f2tf(rb.z); rb.w = f2tf(rb.w);
    };
    auto stage_store = [&](int buf) {
        float* a0 = &As[buf][am0 * SA + ak0];
        a0[0] = f2tf(ra0.x); a0[1] = f2tf(ra0.y); a0[2] = f2tf(ra0.z); a0[3] = f2tf(ra0.w);
        float* a1 = &As[buf][am1 * SA + ak0];
        a1[0] = f2tf(ra1.x); a1[1] = f2tf(ra1.y); a1[2] = f2tf(ra1.z); a1[3] = f2tf(ra1.w);
        *(float4*)&Bs[buf][bk * SBS + bfi] = rb;
    };

    float acc[2][4][4];
#pragma unroll
    for (int i = 0; i < 2; i++)
#pragma unroll
        for (int j = 0; j < 4; j++)
#pragma unroll
            for (int q = 0; q < 4; q++) acc[i][j][q] = 0.f;

    stage_load(0);
    stage_store(0);
    __syncthreads();

    const int nst = FF / BKF;
    for (int ks = 0; ks < nst; ks++) {
        int buf = ks & 1;
        if (ks + 1 < nst) stage_load(ks + 1);
#pragma unroll
        for (int kk = 0; kk < BKF; kk += 8) {
            float a[2][4];
#pragma unroll
            for (int mt = 0; mt < 2; mt++) {
                int rbase = wm * 32 + mt * 16;
                a[mt][0] = As[buf][(rbase + gid)     * SA + kk + tig];
                a[mt][1] = As[buf][(rbase + gid + 8) * SA + kk + tig];
                a[mt][2] = As[buf][(rbase + gid)     * SA + kk + tig + 4];
                a[mt][3] = As[buf][(rbase + gid + 8) * SA + kk + tig + 4];
            }
            float bfr[4][2];
#pragma unroll
            for (int nt = 0; nt < 4; nt++) {
                int cb = wn * 32 + nt * 8 + gid;
                bfr[nt][0] = Bs[buf][(kk + tig)     * SBS + cb];
                bfr[nt][1] = Bs[buf][(kk + tig + 4) * SBS + cb];
            }
#pragma unroll
            for (int mt = 0; mt < 2; mt++)
#pragma unroll
                for (int nt = 0; nt < 4; nt++)
                    mma_tf32_legacy(acc[mt][nt], a[mt], bfr[nt]);
        }
        if (ks + 1 < nst) stage_store(buf ^ 1);
        __syncthreads();
    }

    const int rb0 = mtile * BMF + wm * 32;
    const int cb0 = ctile * BNF + wn * 32;
#pragma unroll
    for (int mt = 0; mt < 2; mt++) {
        int r0 = rb0 + mt * 16 + gid;
        float w0 = g_row_weight[r0];
        float w1 = g_row_weight[r0 + 8];
#pragma unroll
        for (int nt = 0; nt < 4; nt++) {
            int c = cb0 + nt * 8 + tig * 2;
            *(float2*)&g_y[(size_t)r0 * CC + c] =
                make_float2(acc[mt][nt][0] * w0, acc[mt][nt][1] * w0);
            *(float2*)&g_y[(size_t)(r0 + 8) * CC + c] =
                make_float2(acc[mt][nt][2] * w1, acc[mt][nt][3] * w1);
        }
    }
}

// ---------------- 8. combine ----------------
__global__ void combine_kernel(float* __restrict__ out) {
    int i = blockIdx.x * blockDim.x + threadIdx.x;
    if (i < NT * (CC / 4)) {
        int t = i >> 8;
        int c4 = i & 255;
        int r0 = g_row_of[2 * t];
        int r1 = g_row_of[2 * t + 1];
        const float4* y = (const float4*)g_y;
        float4 a = y[(size_t)r0 * 256 + c4];
        float4 b = y[(size_t)r1 * 256 + c4];
        ((float4*)out)[i] = make_float4(a.x + b.x, a.y + b.y, a.z + b.z, a.w + b.w);
    }
}

// ---------------- host: tensor map construction ----------------
typedef CUresult (*EncodeFn)(CUtensorMap*, CUtensorMapDataType, cuuint32_t, void*,
                             const cuuint64_t*, const cuuint64_t*, const cuuint32_t*,
                             const cuuint32_t*, CUtensorMapInterleave, CUtensorMapSwizzle,
                             CUtensorMapL2promotion, CUtensorMapFloatOOBfill);

static void make_map2d(EncodeFn enc, CUtensorMap* m, void* ptr,
                       uint64_t d0, uint64_t d1, uint32_t b0, uint32_t b1) {
    cuuint64_t dims[2] = { d0, d1 };
    cuuint64_t strides[1] = { d0 * 4 };
    cuuint32_t box[2] = { b0, b1 };
    cuuint32_t es[2] = { 1, 1 };
    enc(m, CU_TENSOR_MAP_DATA_TYPE_FLOAT32, 2, ptr, dims, strides, box, es,
        CU_TENSOR_MAP_INTERLEAVE_NONE, CU_TENSOR_MAP_SWIZZLE_128B,
        CU_TENSOR_MAP_L2_PROMOTION_L2_128B, CU_TENSOR_MAP_FLOAT_OOB_FILL_NONE);
}
static void make_map3d(EncodeFn enc, CUtensorMap* m, void* ptr,
                       uint64_t d0, uint64_t d1, uint64_t d2, uint32_t b0, uint32_t b1) {
    cuuint64_t dims[3] = { d0, d1, d2 };
    cuuint64_t strides[2] = { d0 * 4, d0 * d1 * 4 };
    cuuint32_t box[3] = { b0, b1, 1 };
    cuuint32_t es[3] = { 1, 1, 1 };
    enc(m, CU_TENSOR_MAP_DATA_TYPE_FLOAT32, 3, ptr, dims, strides, box, es,
        CU_TENSOR_MAP_INTERLEAVE_NONE, CU_TENSOR_MAP_SWIZZLE_128B,
        CU_TENSOR_MAP_L2_PROMOTION_L2_128B, CU_TENSOR_MAP_FLOAT_OOB_FILL_NONE);
}

extern "C" void kernel_launch(void* const* d_in, const int* in_sizes, int n_in,
                              void* d_out, int out_size) {
    const float* x     = (const float*)d_in[0];
    const float* wgate = (const float*)d_in[1];
    const float* wg    = (const float*)d_in[2];
    const float* wu    = (const float*)d_in[3];
    const float* wd    = (const float*)d_in[4];
    float* out = (float*)d_out;

    EncodeFn enc = nullptr;
    cudaDriverEntryPointQueryResult qr = cudaDriverEntryPointSymbolNotFound;
    cudaError_t qerr = cudaGetDriverEntryPoint("cuTensorMapEncodeTiled", (void**)&enc,
                                               cudaEnableDefault, &qr);
    bool tc_ok = (qerr == cudaSuccess) && (qr == cudaDriverEntryPointSuccess) && (enc != nullptr);

    bool tc_certain = false;
    if (tc_ok) {
        cudaFuncAttributes fa;
        if (cudaFuncGetAttributes(&fa, gemm1_kernel) == cudaSuccess && fa.numRegs > 32)
            tc_certain = true;
    }

    void *p_gx, *p_wgT, *p_wuT, *p_wdT, *p_h;
    cudaGetSymbolAddress(&p_gx, g_gx);
    cudaGetSymbolAddress(&p_wgT, g_wgT);
    cudaGetSymbolAddress(&p_wuT, g_wuT);
    cudaGetSymbolAddress(&p_wdT, g_wdT);
    cudaGetSymbolAddress(&p_h, g_h);

    CUtensorMap m_gx, m_wgT, m_wuT, m_h, m_wdT;
    if (tc_ok) {
        make_map3d(enc, &m_gx, p_gx, CC, RMAX2, 1, 32, 128);   // half-tile A boxes (cg2)
        make_map3d(enc, &m_wgT, p_wgT, CC, FF, NE, 32, 128);
        make_map3d(enc, &m_wuT, p_wuT, CC, FF, NE, 32, 128);
        make_map2d(enc, &m_h, p_h, FP, RMAX2, 32, 256);
        make_map3d(enc, &m_wdT, p_wdT, FF, CC, NE, 32, 256);
        cudaFuncSetAttribute(gemm1_kernel, cudaFuncAttributeMaxDynamicSharedMemorySize, 199680);
        cudaFuncSetAttribute(gemm2_kernel, cudaFuncAttributeMaxDynamicSharedMemorySize, 199680);
    }

    init0_kernel<<<1, 32>>>();
    prep_kernel<<<NB_PREP, 256>>>(x, wgate, wg, wu, wd,
                                  (float*)p_wgT, (float*)p_wuT, (float*)p_wdT);
    scan_kernel<<<1, 32>>>();
    assign_permute_kernel<<<NT / 8, 256>>>(x);
    if (tc_ok) {
        cudaLaunchConfig_t cfg = {};
        cfg.gridDim = dim3(2 * (FP / 256), PT, 1);   // 22 x 72, clusters of 2 along x
        cfg.blockDim = dim3(128, 1, 1);
        cfg.dynamicSmemBytes = 199680;
        cfg.stream = 0;
        cudaLaunchAttribute at[1];
        at[0].id = cudaLaunchAttributeClusterDimension;
        at[0].val.clusterDim.x = 2; at[0].val.clusterDim.y = 1; at[0].val.clusterDim.z = 1;
        cfg.attrs = at;
        cfg.numAttrs = 1;
        cudaLaunchKernelEx(&cfg, gemm1_kernel, m_gx, m_wgT, m_wuT);
    }
    if (!tc_certain) gemm1_fb_kernel<<<dim3(FF / BNF, MT_FB), 256>>>(x, wg, wu);
    if (tc_ok) gemm2_kernel<<<dim3(CC / 256, PT), 128, 199680>>>(m_h, m_wdT);
    if (!tc_certain) gemm2_fb_kernel<<<dim3(CC / BNF, MT_FB), 256>>>(wd);
    combine_kernel<<<(NT * (CC / 4) + 255) / 256, 256>>>(out);
}

// round 17
// speedup vs baseline: 1.0697x; 1.0697x over previous
#include <cuda_runtime.h>
#include <cuda.h>
#include <math.h>
#include <stdint.h>

// ---------------- problem constants ----------------
#define CC    1024           // model dim
#define NE    8              // experts
#define FF    2752           // ffn dim
#define FP    2816           // ffn dim padded to 128*22
#define NT    8192           // tokens
#define NRR   16384          // routed rows (NT*2)
#define RMAX2 18432          // NRR + NE*256 (per-expert pad to 256)
#define PT    72             // pair tiles (RMAX2/256)
#define MT_FB 144            // 128-row tiles (fallback)
#define NK1   32             // CC/32 k-steps (gemm1)
#define NK2   86             // FF/32 k-steps (gemm2; h cols FF..FP are exact zeros)
#define ST1   3              // pipeline stages gemm1
#define ST2   3              // pipeline stages gemm2
#define STAGE1 65536         // A 32KB + Bg 16KB + Bu 16KB
#define STAGE2 65536         // A 32KB + B 32KB (N=256)
#define IDESC_TF32      0x8200910u // cF32|aTF32|bTF32|(128/8)<<17|(128/16)<<24
#define IDESC_TF32_N256 0x8400910u // same with N=256
// fused prep grid layout
#define NB_TR1   (86 * 32 * NE)        // wg transpose blocks (FF/32 x CC/32 x NE) = 22016
#define NB_TR    (3 * NB_TR1)          // wg, wu, wd
#define NB_ROW   (RMAX2 / 256)         // 72
#define NB_GATE  (NT / 8)              // 1024
#define NB_PREP  (NB_TR + NB_ROW + NB_GATE)
// fallback tiling
#define BMF  128
#define BNF  64
#define BKF  16
#define SA   20
#define SBS  72

// tcgen05 availability: only in arch-specific / family-specific device passes.
#if defined(__CUDA_ARCH_FEAT_SM103_ALL) || defined(__CUDA_ARCH_FEAT_SM100_ALL) || \
    defined(__CUDA_ARCH_FEAT_SM101_ALL) || defined(__CUDA_ARCH_FAMILY_SPECIFIC__)
#define TC_ENABLED 1
#else
#define TC_ENABLED 0
#endif

// ---------------- scratch (__device__ globals) ----------------
__device__ int   g_tc;
__device__ int   g_count[NE];
__device__ int   g_cursor[NE];
__device__ int   g_off[NE + 1];
__device__ int   g_tile_expert[PT];
__device__ int   g_tok_e[NRR];
__device__ float g_tok_w[NRR];
__device__ int   g_row_token[RMAX2];
__device__ float g_row_weight[RMAX2];
__device__ int   g_row_of[NRR];
__device__ __align__(1024) float g_gx[(size_t)RMAX2 * CC];
__device__ __align__(1024) float g_wgT[(size_t)NE * FF * CC];
__device__ __align__(1024) float g_wuT[(size_t)NE * FF * CC];
__device__ __align__(1024) float g_wdT[(size_t)NE * CC * FF];
__device__ __align__(1024) float g_h[(size_t)RMAX2 * FP];
__device__ __align__(1024) float g_y[(size_t)RMAX2 * CC];

// ---------------- PTX helpers ----------------
__device__ __forceinline__ float f2tf(float x) {
    unsigned u; asm("cvt.rna.tf32.f32 %0, %1;" : "=r"(u) : "f"(x));
    return __uint_as_float(u);
}
__device__ __forceinline__ uint32_t smem_u32(const void* p) {
    uint32_t a;
    asm("{ .reg .u64 t; cvta.to.shared.u64 t, %1; cvt.u32.u64 %0, t; }" : "=r"(a) : "l"(p));
    return a;
}
#if TC_ENABLED
__device__ __forceinline__ uint32_t elect_one() {
    uint32_t p;
    asm volatile("{ .reg .pred p; elect.sync _|p, 0xFFFFFFFF; selp.b32 %0, 1, 0, p; }" : "=r"(p));
    return p;
}
#define MBAR_INIT(a, n) asm volatile("mbarrier.init.shared.b64 [%0], %1;" :: "r"(a), "r"((uint32_t)(n)) : "memory")
#define MBAR_EXPECT_TX(a, b) asm volatile("mbarrier.arrive.expect_tx.shared.b64 _, [%0], %1;" :: "r"(a), "r"((uint32_t)(b)) : "memory")
#define MBAR_WAIT(a, p) do { \
    uint32_t _m = (a), _p = (p), _d; \
    asm volatile("{ .reg .pred q; mbarrier.try_wait.parity.acquire.cta.shared::cta.b64 q, [%1], %2; selp.b32 %0, 1, 0, q; }" \
        : "=r"(_d) : "r"(_m), "r"(_p) : "memory"); \
    if (!_d) { \
        asm volatile("{ .reg .pred Q;\nWL%=:\n mbarrier.try_wait.parity.acquire.cta.shared::cta.b64 Q, [%0], %1, 0x989680;\n @Q bra.uni WD%=;\n bra.uni WL%=;\nWD%=:\n}" \
            :: "r"(_m), "r"(_p) : "memory"); \
    } } while (0)
#define FENCE_ASYNC() asm volatile("fence.proxy.async.shared::cta;" ::: "memory")
#define TMA_2D(sm, mp, c0, c1, mb) \
    asm volatile("cp.async.bulk.tensor.2d.shared::cta.global.tile.mbarrier::complete_tx::bytes [%0], [%1, {%2, %3}], [%4];" \
        :: "r"(sm), "l"(mp), "r"(c0), "r"(c1), "r"(mb) : "memory")
#define TMA_3D(sm, mp, c0, c1, c2, mb) \
    asm volatile("cp.async.bulk.tensor.3d.shared::cta.global.tile.mbarrier::complete_tx::bytes [%0], [%1, {%2, %3, %4}], [%5];" \
        :: "r"(sm), "l"(mp), "r"(c0), "r"(c1), "r"(c2), "r"(mb) : "memory")
#define TC_ALLOC(sm, n)   asm volatile("tcgen05.alloc.cta_group::1.sync.aligned.shared::cta.b32 [%0], %1;" :: "r"(sm), "r"((uint32_t)(n)) : "memory")
#define TC_DEALLOC(t, n)  asm volatile("tcgen05.dealloc.cta_group::1.sync.aligned.b32 %0, %1;" :: "r"(t), "r"((uint32_t)(n)))
#define TC_COMMIT(mb)     asm volatile("tcgen05.commit.cta_group::1.mbarrier::arrive::one.shared::cluster.b64 [%0];" :: "r"(mb) : "memory")
#define TC_FENCE_AFTER()  asm volatile("tcgen05.fence::after_thread_sync;" ::: "memory")
#define TC_FENCE_BEFORE() asm volatile("tcgen05.fence::before_thread_sync;" ::: "memory")
#define TC_WAIT_LD()      asm volatile("tcgen05.wait::ld.sync.aligned;" ::: "memory")
#define TC_MMA(d, ad, bd, idsc, en) do { \
    uint32_t _e = (en) ? 1u : 0u, _z = 0u; \
    asm volatile("{ .reg .pred p; setp.ne.u32 p, %5, 0;\n" \
        "tcgen05.mma.cta_group::1.kind::tf32 [%0], %1, %2, %3, {%4, %4, %4, %4}, p;\n}" \
        :: "r"(d), "l"(ad), "l"(bd), "r"(idsc), "r"(_z), "r"(_e) : "memory"); \
    } while (0)
#define TC_LD_X32(r, t) \
    asm volatile("tcgen05.ld.sync.aligned.32x32b.x32.b32 " \
        "{%0,%1,%2,%3,%4,%5,%6,%7,%8,%9,%10,%11,%12,%13,%14,%15," \
        "%16,%17,%18,%19,%20,%21,%22,%23,%24,%25,%26,%27,%28,%29,%30,%31}, [%32];" \
        : "=r"((r)[0]),"=r"((r)[1]),"=r"((r)[2]),"=r"((r)[3]),"=r"((r)[4]),"=r"((r)[5]),"=r"((r)[6]),"=r"((r)[7]), \
          "=r"((r)[8]),"=r"((r)[9]),"=r"((r)[10]),"=r"((r)[11]),"=r"((r)[12]),"=r"((r)[13]),"=r"((r)[14]),"=r"((r)[15]), \
          "=r"((r)[16]),"=r"((r)[17]),"=r"((r)[18]),"=r"((r)[19]),"=r"((r)[20]),"=r"((r)[21]),"=r"((r)[22]),"=r"((r)[23]), \
          "=r"((r)[24]),"=r"((r)[25]),"=r"((r)[26]),"=r"((r)[27]),"=r"((r)[28]),"=r"((r)[29]),"=r"((r)[30]),"=r"((r)[31]) \
        : "r"(t))

static __device__ __forceinline__ uint64_t mk_desc(uint32_t addr) {
    // SW128, version=1 (Blackwell), SBO=64, LBO=1  (128B rows, 1024B atoms)
    uint64_t d = (uint64_t(2) << 61) | (uint64_t(1) << 46) | (uint64_t(64) << 32) | (uint64_t(1) << 16);
    return d | ((uint64_t)(addr >> 4) & 0x3FFF);
}
#endif  // TC_ENABLED

// legacy mma.sync tf32 (works on any pass)
__device__ __forceinline__ void mma_tf32_legacy(float d[4], const float a[4], const float b[2]) {
    asm volatile(
        "mma.sync.aligned.m16n8k8.row.col.f32.tf32.tf32.f32 "
        "{%0,%1,%2,%3}, {%4,%5,%6,%7}, {%8,%9}, {%0,%1,%2,%3};\n"
        : "+f"(d[0]), "+f"(d[1]), "+f"(d[2]), "+f"(d[3])
        : "r"(__float_as_uint(a[0])), "r"(__float_as_uint(a[1])),
          "r"(__float_as_uint(a[2])), "r"(__float_as_uint(a[3])),
          "r"(__float_as_uint(b[0])), "r"(__float_as_uint(b[1])));
}

// ---------------- 0a. init0: zero gate counters (must precede prep) -----------
__global__ void init0_kernel() {
    int i = threadIdx.x;
    if (i < NE) { g_count[i] = 0; g_cursor[i] = 0; }
    if (i == 0) g_tc = 0;
}

// ---------------- 0b. fused prep: row-init + gate + 3 transposes --------------
__global__ __launch_bounds__(256) void prep_kernel(
    const float* __restrict__ x, const float* __restrict__ wgate,
    const float* __restrict__ wg, const float* __restrict__ wu,
    const float* __restrict__ wd,
    float* __restrict__ wgT, float* __restrict__ wuT, float* __restrict__ wdT)
{
    __shared__ float sw[NE * CC];
    __shared__ float tt[32][33];

    const int b = blockIdx.x;
    const int tid = threadIdx.x;

    if (b < NB_TR) {
        int which = b / NB_TR1;
        int rem = b % NB_TR1;
        const float* in; float* out; int R, Q, bx, by, e;
        if (which < 2) {
            in = (which == 0) ? wg : wu;
            out = (which == 0) ? wgT : wuT;
            R = CC; Q = FF;
            bx = rem % 86; by = (rem / 86) % 32; e = rem / (86 * 32);
        } else {
            in = wd; out = wdT;
            R = FF; Q = CC;
            bx = rem % 32; by = (rem / 32) % 86; e = rem / (32 * 86);
        }
        const float* src = in + (size_t)e * R * Q;
        float* dst = out + (size_t)e * R * Q;
        int r0 = by * 32, q0 = bx * 32;
        int tx = tid & 31, ty = tid >> 5;
#pragma unroll
        for (int i = ty; i < 32; i += 8)
            tt[i][tx] = src[(size_t)(r0 + i) * Q + q0 + tx];
        __syncthreads();
#pragma unroll
        for (int i = ty; i < 32; i += 8)
            dst[(size_t)(q0 + i) * R + r0 + tx] = f2tf(tt[tx][i]);
        return;
    }
    if (b < NB_TR + NB_ROW) {
        int i = (b - NB_TR) * 256 + tid;
        if (i < RMAX2) { g_row_token[i] = -1; g_row_weight[i] = 0.f; }
        return;
    }
    {
        int gb = b - NB_TR - NB_ROW;
        for (int i = tid * 4; i < NE * CC; i += 256 * 4)
            *(float4*)&sw[i] = *(const float4*)&wgate[i];
        __syncthreads();
        int warp = tid >> 5, lane = tid & 31;
        int t = gb * 8 + warp;
        const float* xt = x + (size_t)t * CC;
        float acc[NE];
#pragma unroll
        for (int e = 0; e < NE; e++) acc[e] = 0.f;
        for (int j = lane; j < CC; j += 32) {
            float xv = xt[j];
#pragma unroll
            for (int e = 0; e < NE; e++) acc[e] += xv * sw[e * CC + j];
        }
#pragma unroll
        for (int off = 16; off > 0; off >>= 1)
#pragma unroll
            for (int e = 0; e < NE; e++) acc[e] += __shfl_xor_sync(0xffffffffu, acc[e], off);
        if (lane == 0) {
            float m = acc[0];
#pragma unroll
            for (int e = 1; e < NE; e++) m = fmaxf(m, acc[e]);
            float p[NE], s = 0.f;
#pragma unroll
            for (int e = 0; e < NE; e++) { p[e] = expf(acc[e] - m); s += p[e]; }
            int i0 = 0; float b0 = p[0];
#pragma unroll
            for (int e = 1; e < NE; e++) if (p[e] > b0) { b0 = p[e]; i0 = e; }
            int i1 = -1; float b1 = -1.f;
#pragma unroll
            for (int e = 0; e < NE; e++) if (e != i0 && p[e] > b1) { b1 = p[e]; i1 = e; }
            float s0 = b0 / s, s1 = b1 / s;
            float den = s0 + s1 + 1e-9f;
            g_tok_e[2 * t] = i0;     g_tok_w[2 * t] = s0 / den;
            g_tok_e[2 * t + 1] = i1; g_tok_w[2 * t + 1] = s1 / den;
            atomicAdd(&g_count[i0], 1);
            atomicAdd(&g_count[i1], 1);
        }
    }
}

// ---------------- 2. scan (pad per-expert to 256) ----------------
__global__ void scan_kernel() {
    if (threadIdx.x == 0 && blockIdx.x == 0) {
        int off = 0;
        for (int e = 0; e < NE; e++) {
            g_off[e] = off;
            off += ((g_count[e] + 255) / 256) * 256;
        }
        g_off[NE] = off;
        int tl = 0;
        for (int e = 0; e < NE; e++) {
            int pairs = (g_off[e + 1] - g_off[e]) / 256;
            for (int i = 0; i < pairs; i++) g_tile_expert[tl++] = e;
        }
        while (tl < PT) g_tile_expert[tl++] = 0;
    }
}

// ---------------- 3. fused assign + permute ----------------
__global__ __launch_bounds__(256) void assign_permute_kernel(const float* __restrict__ x) {
    int warp = threadIdx.x >> 5, lane = threadIdx.x & 31;
    int t = blockIdx.x * 8 + warp;
    int row0 = 0, row1 = 0;
    if (lane == 0) {
        int e0 = g_tok_e[2 * t];
        int p0 = atomicAdd(&g_cursor[e0], 1);
        row0 = g_off[e0] + p0;
        g_row_token[row0] = t;
        g_row_weight[row0] = g_tok_w[2 * t];
        g_row_of[2 * t] = row0;
        int e1 = g_tok_e[2 * t + 1];
        int p1 = atomicAdd(&g_cursor[e1], 1);
        row1 = g_off[e1] + p1;
        g_row_token[row1] = t;
        g_row_weight[row1] = g_tok_w[2 * t + 1];
        g_row_of[2 * t + 1] = row1;
    }
    row0 = __shfl_sync(0xffffffffu, row0, 0);
    row1 = __shfl_sync(0xffffffffu, row1, 0);
    const float4* xs = (const float4*)(x + (size_t)t * CC);
    float4* d0 = (float4*)(g_gx + (size_t)row0 * CC);
    float4* d1 = (float4*)(g_gx + (size_t)row1 * CC);
#pragma unroll
    for (int i = lane; i < CC / 4; i += 32) {
        float4 v = xs[i];
        v.x = f2tf(v.x); v.y = f2tf(v.y); v.z = f2tf(v.z); v.w = f2tf(v.w);
        d0[i] = v;
        d1[i] = v;
    }
}

// ---------------- 6. GEMM1 (tcgen05): h = silu(gx@wg)*(gx@wu) -----------------
// single-issuer; EMPTY wait software-pipelined by one iteration (831us winner)
__global__ __launch_bounds__(128, 1) void gemm1_kernel(
    const __grid_constant__ CUtensorMap tma_a,
    const __grid_constant__ CUtensorMap tma_bg,
    const __grid_constant__ CUtensorMap tma_bu)
{
#if TC_ENABLED
    extern __shared__ char smem[];
    uint32_t sb = smem_u32(smem);
    uint32_t TMP = sb;
    uint32_t FULL = sb + 8;
    uint32_t EMPTY = sb + 8 + 8 * ST1;
    uint32_t DONE = sb + 8 + 16 * ST1;
    uint32_t tiles = (sb + 64 + 1023) & ~1023u;

    const int ftile = blockIdx.x;
    const int pair = blockIdx.y;
    const int e = g_tile_expert[pair];
    const int tid = threadIdx.x, wid = tid >> 5, lane = tid & 31;

    if (tid == 0) {
        g_tc = 1;
        for (int s = 0; s < ST1; s++) { MBAR_INIT(FULL + 8 * s, 1); MBAR_INIT(EMPTY + 8 * s, 1); }
        MBAR_INIT(DONE, 1);
        FENCE_ASYNC();
    }
    if (wid == 0) TC_ALLOC(TMP, 512);
    __syncthreads();
    uint32_t tmem;
    asm volatile("ld.shared.b32 %0, [%1];" : "=r"(tmem) : "r"(TMP));

    if (wid == 0 && elect_one()) {
        auto tma_stage = [&](int s, int ks) {
            uint32_t a = tiles + s * STAGE1;
            MBAR_EXPECT_TX(FULL + 8 * s, STAGE1);
            TMA_2D(a,          &tma_a,  ks * 32, pair * 256, FULL + 8 * s);
            TMA_3D(a + 32768,  &tma_bg, ks * 32, ftile * 128, e, FULL + 8 * s);
            TMA_3D(a + 49152,  &tma_bu, ks * 32, ftile * 128, e, FULL + 8 * s);
        };
        for (int j = 0; j < ST1; j++) tma_stage(j, j);
        for (int i = 0; i < NK1; i++) {
            int s = i % ST1;
            MBAR_WAIT(FULL + 8 * s, (uint32_t)(i / ST1) & 1);
            uint64_t ad = mk_desc(tiles + s * STAGE1);
            uint64_t bg = mk_desc(tiles + s * STAGE1 + 32768);
            uint64_t bu = mk_desc(tiles + s * STAGE1 + 49152);
#pragma unroll
            for (int k8 = 0; k8 < 4; k8++) {
                bool en = (i > 0) || (k8 > 0);
                TC_MMA(tmem + 0,   ad + k8 * 2,        bg + k8 * 2, IDESC_TF32, en);
                TC_MMA(tmem + 128, ad + 1024 + k8 * 2, bg + k8 * 2, IDESC_TF32, en);
                TC_MMA(tmem + 256, ad + k8 * 2,        bu + k8 * 2, IDESC_TF32, en);
                TC_MMA(tmem + 384, ad + 1024 + k8 * 2, bu + k8 * 2, IDESC_TF32, en);
            }
            TC_COMMIT(EMPTY + 8 * s);
            if (i >= 1 && i <= NK1 - ST1) {
                int s2 = (i - 1) % ST1;
                MBAR_WAIT(EMPTY + 8 * s2, (uint32_t)((i - 1) / ST1) & 1);
                tma_stage(s2, (i - 1) + ST1);
            }
        }
        TC_COMMIT(DONE);
    }
    __syncthreads();
    MBAR_WAIT(DONE, 0);
    TC_FENCE_AFTER();

#pragma unroll
    for (int m = 0; m < 2; m++) {
        int row = pair * 256 + m * 128 + wid * 32 + lane;
        size_t hb = (size_t)row * FP + ftile * 128;
#pragma unroll
        for (int c = 0; c < 4; c++) {
            uint32_t gr[32], ur[32];
            TC_LD_X32(gr, tmem + m * 128 + c * 32);
            TC_LD_X32(ur, tmem + 256 + m * 128 + c * 32);
            TC_WAIT_LD();
            float buf[32];
#pragma unroll
            for (int q = 0; q < 32; q++) {
                float g = __uint_as_float(gr[q]);
                float u = __uint_as_float(ur[q]);
                buf[q] = f2tf(g / (1.f + expf(-g)) * u);
            }
#pragma unroll
            for (int q = 0; q < 32; q += 4)
                *(float4*)&g_h[hb + c * 32 + q] = make_float4(buf[q], buf[q+1], buf[q+2], buf[q+3]);
        }
    }
    TC_FENCE_BEFORE();
    __syncthreads();
    if (wid == 0) TC_DEALLOC(tmem, 512);
#endif
}

// ---------------- 7. GEMM2 (tcgen05): y = weight * (h @ wd), N=256 ------------
__global__ __launch_bounds__(128, 1) void gemm2_kernel(
    const __grid_constant__ CUtensorMap tma_a,
    const __grid_constant__ CUtensorMap tma_b)
{
#if TC_ENABLED
    extern __shared__ char smem[];
    uint32_t sb = smem_u32(smem);
    uint32_t TMP = sb;
    uint32_t FULL = sb + 8;
    uint32_t EMPTY = sb + 8 + 8 * ST2;
    uint32_t DONE = sb + 8 + 16 * ST2;
    uint32_t tiles = (sb + 80 + 1023) & ~1023u;

    const int ctile = blockIdx.x;            // 4 tiles of 256 cols
    const int pair = blockIdx.y;
    const int e = g_tile_expert[pair];
    const int tid = threadIdx.x, wid = tid >> 5, lane = tid & 31;

    if (tid == 0) {
        for (int s = 0; s < ST2; s++) { MBAR_INIT(FULL + 8 * s, 1); MBAR_INIT(EMPTY + 8 * s, 1); }
        MBAR_INIT(DONE, 1);
        FENCE_ASYNC();
    }
    if (wid == 0) TC_ALLOC(TMP, 512);
    __syncthreads();
    uint32_t tmem;
    asm volatile("ld.shared.b32 %0, [%1];" : "=r"(tmem) : "r"(TMP));

    if (wid == 0 && elect_one()) {
        auto tma_stage = [&](int s, int ks) {
            uint32_t a = tiles + s * STAGE2;
            MBAR_EXPECT_TX(FULL + 8 * s, STAGE2);
            TMA_2D(a,         &tma_a, ks * 32, pair * 256, FULL + 8 * s);
            TMA_3D(a + 32768, &tma_b, ks * 32, ctile * 256, e, FULL + 8 * s);
        };
        for (int j = 0; j < ST2; j++) tma_stage(j, j);
        for (int i = 0; i < NK2; i++) {
            int s = i % ST2;
            MBAR_WAIT(FULL + 8 * s, (uint32_t)(i / ST2) & 1);
            uint64_t ad = mk_desc(tiles + s * STAGE2);
            uint64_t bd = mk_desc(tiles + s * STAGE2 + 32768);
#pragma unroll
            for (int k8 = 0; k8 < 4; k8++) {
                bool en = (i > 0) || (k8 > 0);
                TC_MMA(tmem + 0,   ad + k8 * 2,        bd + k8 * 2, IDESC_TF32_N256, en);
                TC_MMA(tmem + 256, ad + 1024 + k8 * 2, bd + k8 * 2, IDESC_TF32_N256, en);
            }
            TC_COMMIT(EMPTY + 8 * s);
            if (i >= 1 && i <= NK2 - ST2) {
                int s2 = (i - 1) % ST2;
                MBAR_WAIT(EMPTY + 8 * s2, (uint32_t)((i - 1) / ST2) & 1);
                tma_stage(s2, (i - 1) + ST2);
            }
        }
        TC_COMMIT(DONE);
    }
    __syncthreads();
    MBAR_WAIT(DONE, 0);
    TC_FENCE_AFTER();

#pragma unroll
    for (int m = 0; m < 2; m++) {
        int row = pair * 256 + m * 128 + wid * 32 + lane;
        float w = g_row_weight[row];
        size_t yb = (size_t)row * CC + ctile * 256;
#pragma unroll
        for (int c = 0; c < 8; c++) {
            uint32_t yr[32];
            TC_LD_X32(yr, tmem + m * 256 + c * 32);
            TC_WAIT_LD();
            float buf[32];
#pragma unroll
            for (int q = 0; q < 32; q++) buf[q] = __uint_as_float(yr[q]) * w;
#pragma unroll
            for (int q = 0; q < 32; q += 4)
                *(float4*)&g_y[yb + c * 32 + q] = make_float4(buf[q], buf[q+1], buf[q+2], buf[q+3]);
        }
    }
    TC_FENCE_BEFORE();
    __syncthreads();
    if (wid == 0) TC_DEALLOC(tmem, 512);
#endif
}

// ---------------- 6b. GEMM1 fallback (mma.sync, validated) --------------------
__global__ __launch_bounds__(256) void gemm1_fb_kernel(
    const float* __restrict__ x, const float* __restrict__ wg, const float* __restrict__ wu)
{
    if (g_tc != 0) return;
    __shared__ float As[2][BMF * SA];
    __shared__ float Bgs[2][BKF * SBS];
    __shared__ float Bus[2][BKF * SBS];
    __shared__ int stok[BMF];

    const int ftile = blockIdx.x;
    const int mtile = blockIdx.y;
    const int tid = threadIdx.x;
    const int e = g_tile_expert[mtile >> 1];
    const float* wgE = wg + (size_t)e * CC * FF;
    const float* wuE = wu + (size_t)e * CC * FF;

    if (tid < BMF) stok[tid] = g_row_token[mtile * BMF + tid];
    __syncthreads();

    const int warp = tid >> 5, lane = tid & 31;
    const int wm = warp >> 1, wn = warp & 1;
    const int gid = lane >> 2, tig = lane & 3;
    const int am0 = tid >> 2, ak0 = (tid & 3) * 4;
    const int am1 = (tid + 256) >> 2;
    const int bk = tid >> 4, bfi = (tid & 15) * 4;
    const int fbase = ftile * BNF;

    float4 ra0, ra1, rbg, rbu;
    auto stage_load = [&](int ks) {
        int kb = ks * BKF;
        int t0 = stok[am0];
        ra0 = make_float4(0.f, 0.f, 0.f, 0.f);
        if (t0 >= 0) ra0 = *(const float4*)(x + (size_t)t0 * CC + kb + ak0);
        int t1 = stok[am1];
        ra1 = make_float4(0.f, 0.f, 0.f, 0.f);
        if (t1 >= 0) ra1 = *(const float4*)(x + (size_t)t1 * CC + kb + ak0);
        rbg = *(const float4*)(wgE + (size_t)(kb + bk) * FF + fbase + bfi);
        rbu = *(const float4*)(wuE + (size_t)(kb + bk) * FF + fbase + bfi);
        rbg.x = f2tf(rbg.x); rbg.y = f2tf(rbg.y); rbg.z = f2tf(rbg.z); rbg.w = f2tf(rbg.w);
        rbu.x = f2tf(rbu.x); rbu.y = f2tf(rbu.y); rbu.z = f2tf(rbu.z); rbu.w = f2tf(rbu.w);
    };
    auto stage_store = [&](int buf) {
        float* a0 = &As[buf][am0 * SA + ak0];
        a0[0] = f2tf(ra0.x); a0[1] = f2tf(ra0.y); a0[2] = f2tf(ra0.z); a0[3] = f2tf(ra0.w);
        float* a1 = &As[buf][am1 * SA + ak0];
        a1[0] = f2tf(ra1.x); a1[1] = f2tf(ra1.y); a1[2] = f2tf(ra1.z); a1[3] = f2tf(ra1.w);
        *(float4*)&Bgs[buf][bk * SBS + bfi] = rbg;
        *(float4*)&Bus[buf][bk * SBS + bfi] = rbu;
    };

    float accg[2][4][4], accu[2][4][4];
#pragma unroll
    for (int i = 0; i < 2; i++)
#pragma unroll
        for (int j = 0; j < 4; j++)
#pragma unroll
            for (int q = 0; q < 4; q++) { accg[i][j][q] = 0.f; accu[i][j][q] = 0.f; }

    stage_load(0);
    stage_store(0);
    __syncthreads();

    const int nst = CC / BKF;
    for (int ks = 0; ks < nst; ks++) {
        int buf = ks & 1;
        if (ks + 1 < nst) stage_load(ks + 1);
#pragma unroll
        for (int kk = 0; kk < BKF; kk += 8) {
            float a[2][4];
#pragma unroll
            for (int mt = 0; mt < 2; mt++) {
                int rb = wm * 32 + mt * 16;
                a[mt][0] = As[buf][(rb + gid)     * SA + kk + tig];
                a[mt][1] = As[buf][(rb + gid + 8) * SA + kk + tig];
                a[mt][2] = As[buf][(rb + gid)     * SA + kk + tig + 4];
                a[mt][3] = As[buf][(rb + gid + 8) * SA + kk + tig + 4];
            }
            float bg[4][2], bu[4][2];
#pragma unroll
            for (int nt = 0; nt < 4; nt++) {
                int cb = wn * 32 + nt * 8 + gid;
                bg[nt][0] = Bgs[buf][(kk + tig)     * SBS + cb];
                bg[nt][1] = Bgs[buf][(kk + tig + 4) * SBS + cb];
                bu[nt][0] = Bus[buf][(kk + tig)     * SBS + cb];
                bu[nt][1] = Bus[buf][(kk + tig + 4) * SBS + cb];
            }
#pragma unroll
            for (int mt = 0; mt < 2; mt++)
#pragma unroll
                for (int nt = 0; nt < 4; nt++) {
                    mma_tf32_legacy(accg[mt][nt], a[mt], bg[nt]);
                    mma_tf32_legacy(accu[mt][nt], a[mt], bu[nt]);
                }
        }
        if (ks + 1 < nst) stage_store(buf ^ 1);
        __syncthreads();
    }

    const int rb0 = mtile * BMF + wm * 32;
    const int cb0 = ftile * BNF + wn * 32;
#pragma unroll
    for (int mt = 0; mt < 2; mt++) {
        int r0 = rb0 + mt * 16 + gid;
#pragma unroll
        for (int nt = 0; nt < 4; nt++) {
            int c = cb0 + nt * 8 + tig * 2;
            float g0 = accg[mt][nt][0], g1 = accg[mt][nt][1];
            float g2 = accg[mt][nt][2], g3 = accg[mt][nt][3];
            float h0 = g0 / (1.f + expf(-g0)) * accu[mt][nt][0];
            float h1 = g1 / (1.f + expf(-g1)) * accu[mt][nt][1];
            float h2 = g2 / (1.f + expf(-g2)) * accu[mt][nt][2];
            float h3 = g3 / (1.f + expf(-g3)) * accu[mt][nt][3];
            *(float2*)&g_h[(size_t)r0 * FP + c]       = make_float2(h0, h1);
            *(float2*)&g_h[(size_t)(r0 + 8) * FP + c] = make_float2(h2, h3);
        }
    }
}

// ---------------- 7b. GEMM2 fallback ------------------------------------------
__global__ __launch_bounds__(256) void gemm2_fb_kernel(const float* __restrict__ wd)
{
    if (g_tc != 0) return;
    __shared__ float As[2][BMF * SA];
    __shared__ float Bs[2][BKF * SBS];

    const int ctile = blockIdx.x;
    const int mtile = blockIdx.y;
    const int tid = threadIdx.x;
    const int e = g_tile_expert[mtile >> 1];
    const float* wdE = wd + (size_t)e * FF * CC;

    const int warp = tid >> 5, lane = tid & 31;
    const int wm = warp >> 1, wn = warp & 1;
    const int gid = lane >> 2, tig = lane & 3;
    const int am0 = tid >> 2, ak0 = (tid & 3) * 4;
    const int am1 = (tid + 256) >> 2;
    const int bk = tid >> 4, bfi = (tid & 15) * 4;
    const int cbase = ctile * BNF;
    const size_t hrow0 = (size_t)(mtile * BMF + am0) * FP;
    const size_t hrow1 = (size_t)(mtile * BMF + am1) * FP;

    float4 ra0, ra1, rb;
    auto stage_load = [&](int ks) {
        int kb = ks * BKF;
        ra0 = *(const float4*)(g_h + hrow0 + kb + ak0);
        ra1 = *(const float4*)(g_h + hrow1 + kb + ak0);
        rb  = *(const float4*)(wdE + (size_t)(kb + bk) * CC + cbase + bfi);
        rb.x = f2tf(rb.x); rb.y = f2tf(rb.y); rb.z = f2tf(rb.z); rb.w = f2tf(rb.w);
    };
    auto stage_store = [&](int buf) {
        float* a0 = &As[buf][am0 * SA + ak0];
        a0[0] = f2tf(ra0.x); a0[1] = f2tf(ra0.y); a0[2] = f2tf(ra0.z); a0[3] = f2tf(ra0.w);
        float* a1 = &As[buf][am1 * SA + ak0];
        a1[0] = f2tf(ra1.x); a1[1] = f2tf(ra1.y); a1[2] = f2tf(ra1.z); a1[3] = f2tf(ra1.w);
        *(float4*)&Bs[buf][bk * SBS + bfi] = rb;
    };

    float acc[2][4][4];
#pragma unroll
    for (int i = 0; i < 2; i++)
#pragma unroll
        for (int j = 0; j < 4; j++)
#pragma unroll
            for (int q = 0; q < 4; q++) acc[i][j][q] = 0.f;

    stage_load(0);
    stage_store(0);
    __syncthreads();

    const int nst = FF / BKF;
    for (int ks = 0; ks < nst; ks++) {
        int buf = ks & 1;
        if (ks + 1 < nst) stage_load(ks + 1);
#pragma unroll
        for (int kk = 0; kk < BKF; kk += 8) {
            float a[2][4];
#pragma unroll
            for (int mt = 0; mt < 2; mt++) {
                int rbase = wm * 32 + mt * 16;
                a[mt][0] = As[buf][(rbase + gid)     * SA + kk + tig];
                a[mt][1] = As[buf][(rbase + gid + 8) * SA + kk + tig];
                a[mt][2] = As[buf][(rbase + gid)     * SA + kk + tig + 4];
                a[mt][3] = As[buf][(rbase + gid + 8) * SA + kk + tig + 4];
            }
            float bfr[4][2];
#pragma unroll
            for (int nt = 0; nt < 4; nt++) {
                int cb = wn * 32 + nt * 8 + gid;
                bfr[nt][0] = Bs[buf][(kk + tig)     * SBS + cb];
                bfr[nt][1] = Bs[buf][(kk + tig + 4) * SBS + cb];
            }
#pragma unroll
            for (int mt = 0; mt < 2; mt++)
#pragma unroll
                for (int nt = 0; nt < 4; nt++)
                    mma_tf32_legacy(acc[mt][nt], a[mt], bfr[nt]);
        }
        if (ks + 1 < nst) stage_store(buf ^ 1);
        __syncthreads();
    }

    const int rb0 = mtile * BMF + wm * 32;
    const int cb0 = ctile * BNF + wn * 32;
#pragma unroll
    for (int mt = 0; mt < 2; mt++) {
        int r0 = rb0 + mt * 16 + gid;
        float w0 = g_row_weight[r0];
        float w1 = g_row_weight[r0 + 8];
#pragma unroll
        for (int nt = 0; nt < 4; nt++) {
            int c = cb0 + nt * 8 + tig * 2;
            *(float2*)&g_y[(size_t)r0 * CC + c] =
                make_float2(acc[mt][nt][0] * w0, acc[mt][nt][1] * w0);
            *(float2*)&g_y[(size_t)(r0 + 8) * CC + c] =
                make_float2(acc[mt][nt][2] * w1, acc[mt][nt][3] * w1);
        }
    }
}

// ---------------- 8. combine ----------------
__global__ void combine_kernel(float* __restrict__ out) {
    int i = blockIdx.x * blockDim.x + threadIdx.x;
    if (i < NT * (CC / 4)) {
        int t = i >> 8;
        int c4 = i & 255;
        int r0 = g_row_of[2 * t];
        int r1 = g_row_of[2 * t + 1];
        const float4* y = (const float4*)g_y;
        float4 a = y[(size_t)r0 * 256 + c4];
        float4 b = y[(size_t)r1 * 256 + c4];
        ((float4*)out)[i] = make_float4(a.x + b.x, a.y + b.y, a.z + b.z, a.w + b.w);
    }
}

// ---------------- host: tensor map construction ----------------
typedef CUresult (*EncodeFn)(CUtensorMap*, CUtensorMapDataType, cuuint32_t, void*,
                             const cuuint64_t*, const cuuint64_t*, const cuuint32_t*,
                             const cuuint32_t*, CUtensorMapInterleave, CUtensorMapSwizzle,
                             CUtensorMapL2promotion, CUtensorMapFloatOOBfill);

static void make_map2d(EncodeFn enc, CUtensorMap* m, void* ptr,
                       uint64_t d0, uint64_t d1, uint32_t b0, uint32_t b1) {
    cuuint64_t dims[2] = { d0, d1 };
    cuuint64_t strides[1] = { d0 * 4 };
    cuuint32_t box[2] = { b0, b1 };
    cuuint32_t es[2] = { 1, 1 };
    enc(m, CU_TENSOR_MAP_DATA_TYPE_FLOAT32, 2, ptr, dims, strides, box, es,
        CU_TENSOR_MAP_INTERLEAVE_NONE, CU_TENSOR_MAP_SWIZZLE_128B,
        CU_TENSOR_MAP_L2_PROMOTION_L2_128B, CU_TENSOR_MAP_FLOAT_OOB_FILL_NONE);
}
static void make_map3d(EncodeFn enc, CUtensorMap* m, void* ptr,
                       uint64_t d0, uint64_t d1, uint64_t d2, uint32_t b0, uint32_t b1) {
    cuuint64_t dims[3] = { d0, d1, d2 };
    cuuint64_t strides[2] = { d0 * 4, d0 * d1 * 4 };
    cuuint32_t box[3] = { b0, b1, 1 };
    cuuint32_t es[3] = { 1, 1, 1 };
    enc(m, CU_TENSOR_MAP_DATA_TYPE_FLOAT32, 3, ptr, dims, strides, box, es,
        CU_TENSOR_MAP_INTERLEAVE_NONE, CU_TENSOR_MAP_SWIZZLE_128B,
        CU_TENSOR_MAP_L2_PROMOTION_L2_128B, CU_TENSOR_MAP_FLOAT_OOB_FILL_NONE);
}

extern "C" void kernel_launch(void* const* d_in, const int* in_sizes, int n_in,
                              void* d_out, int out_size) {
    const float* x     = (const float*)d_in[0];
    const float* wgate = (const float*)d_in[1];
    const float* wg    = (const float*)d_in[2];
    const float* wu    = (const float*)d_in[3];
    const float* wd    = (const float*)d_in[4];
    float* out = (float*)d_out;

    EncodeFn enc = nullptr;
    cudaDriverEntryPointQueryResult qr = cudaDriverEntryPointSymbolNotFound;
    cudaError_t qerr = cudaGetDriverEntryPoint("cuTensorMapEncodeTiled", (void**)&enc,
                                               cudaEnableDefault, &qr);
    bool tc_ok = (qerr == cudaSuccess) && (qr == cudaDriverEntryPointSuccess) && (enc != nullptr);

    bool tc_certain = false;
    if (tc_ok) {
        cudaFuncAttributes fa;
        if (cudaFuncGetAttributes(&fa, gemm1_kernel) == cudaSuccess && fa.numRegs > 32)
            tc_certain = true;
    }

    void *p_gx, *p_wgT, *p_wuT, *p_wdT, *p_h;
    cudaGetSymbolAddress(&p_gx, g_gx);
    cudaGetSymbolAddress(&p_wgT, g_wgT);
    cudaGetSymbolAddress(&p_wuT, g_wuT);
    cudaGetSymbolAddress(&p_wdT, g_wdT);
    cudaGetSymbolAddress(&p_h, g_h);

    CUtensorMap m_gx, m_wgT, m_wuT, m_h, m_wdT;
    if (tc_ok) {
        make_map2d(enc, &m_gx, p_gx, CC, RMAX2, 32, 256);
        make_map3d(enc, &m_wgT, p_wgT, CC, FF, NE, 32, 128);
        make_map3d(enc, &m_wuT, p_wuT, CC, FF, NE, 32, 128);
        make_map2d(enc, &m_h, p_h, FP, RMAX2, 32, 256);
        make_map3d(enc, &m_wdT, p_wdT, FF, CC, NE, 32, 256);
        cudaFuncSetAttribute(gemm1_kernel, cudaFuncAttributeMaxDynamicSharedMemorySize, 199680);
        cudaFuncSetAttribute(gemm2_kernel, cudaFuncAttributeMaxDynamicSharedMemorySize, 199680);
    }

    init0_kernel<<<1, 32>>>();
    prep_kernel<<<NB_PREP, 256>>>(x, wgate, wg, wu, wd,
                                  (float*)p_wgT, (float*)p_wuT, (float*)p_wdT);
    scan_kernel<<<1, 32>>>();
    assign_permute_kernel<<<NT / 8, 256>>>(x);
    if (tc_ok) gemm1_kernel<<<dim3(FP / 128, PT), 128, 199680>>>(m_gx, m_wgT, m_wuT);
    if (!tc_certain) gemm1_fb_kernel<<<dim3(FF / BNF, MT_FB), 256>>>(x, wg, wu);
    if (tc_ok) gemm2_kernel<<<dim3(CC / 256, PT), 128, 199680>>>(m_h, m_wdT);
    if (!tc_certain) gemm2_fb_kernel<<<dim3(CC / BNF, MT_FB), 256>>>(wd);
    combine_kernel<<<(NT * (CC / 4) + 255) / 256, 256>>>(out);
}